// round 7
// baseline (speedup 1.0000x reference)
#include <cuda_runtime.h>
#include <cuda_fp16.h>
#include <cuda_bf16.h>
#include <math.h>

// Problem constants
#define NROWS 512          // 256 pairs * 2 spectra
#define NPEAK 512          // peaks per spectrum
#define GROUPS 3333
#define BOUT 9999          // 3333 * 3
#define H0 1000
#define H1 800
#define H2 800
#define HE 400
#define C0_CHUNKS 80

// -------------------- scratch (device globals; no allocation) --------------------
__device__ float4 g_entries[NROWS * NPEAK];                // 4 MB
__device__ float  g_c0_part[C0_CHUNKS * H0];               // 320 KB
__device__ float  g_c0[H0];
__device__ __half g_w0h[BOUT * H0];                        // 20 MB fp16 copy of w0
__device__ float  g_h0[NROWS * H0];
__device__ float  g_h1[NROWS * H1];
__device__ float  g_h2[NROWS * H2];
__device__ float  g_emb[NROWS * HE];

// -------------------- K1: build compact per-peak entries --------------------
__global__ void __launch_bounds__(512) k_build(
    const float* __restrict__ mz, const float* __restrict__ inten,
    const float* __restrict__ binner_w)
{
    int row = blockIdx.x;
    int p   = threadIdx.x;
    int idx = row * NPEAK + p;
    float m  = mz[idx];
    float it = inten[idx];
    float fb = __fdiv_rn(m, 0.01f);
    int b = (int)fb;
    float4 e;
    if (m >= 0.0f && m < 1000.0f && b >= 0 && b < GROUPS * 30) {
        int g = b / 30;
        int i = b - g * 30;
        float v = sqrtf(it);              // inten ** 0.5
        const float* bw = binner_w + (g * 30 + i) * 3;
        e = make_float4(v * bw[0], v * bw[1], v * bw[2], __int_as_float(3 * g));
    } else {
        e = make_float4(0.f, 0.f, 0.f, __int_as_float(-1));
    }
    g_entries[idx] = e;
}

// -------------------- K2a: c0 partials (bbf @ w0) + fused w0 -> fp16 convert -----
__global__ void __launch_bounds__(256) k_c0_part(
    const float* __restrict__ bbf, const float* __restrict__ w0)
{
    int c = blockIdx.x;
    int k0 = c * 125;
    int k1 = min(k0 + 125, BOUT);
    int t = threadIdx.x;
    if (t >= 250) return;
    float4 acc = make_float4(0.f, 0.f, 0.f, 0.f);
    for (int k = k0; k < k1; k++) {
        float b = bbf[k];
        float4 w = *((const float4*)(w0 + k * H0) + t);
        acc.x += b * w.x; acc.y += b * w.y; acc.z += b * w.z; acc.w += b * w.w;
        // fused conversion: each (k, col) element touched exactly once
        __half2 hlo = __floats2half2_rn(w.x, w.y);
        __half2 hhi = __floats2half2_rn(w.z, w.w);
        uint2 u;
        u.x = *(const unsigned int*)&hlo;
        u.y = *(const unsigned int*)&hhi;
        *((uint2*)(g_w0h + k * H0) + t) = u;
    }
    *((float4*)(g_c0_part + c * H0) + t) = acc;
}

// -------------------- K2b: c0 = b0 + sum(partials), fixed order --------------------
__global__ void __launch_bounds__(256) k_c0_reduce(const float* __restrict__ b0)
{
    int j = blockIdx.x * 256 + threadIdx.x;
    if (j >= H0) return;
    float s = b0[j];
    #pragma unroll 4
    for (int c = 0; c < C0_CHUNKS; c++) s += g_c0_part[c * H0 + j];
    g_c0[j] = s;
}

// -------------------- K3: layer 0 sparse: h0 = relu(xs @ w0 + c0), fp16 weights ----
__global__ void __launch_bounds__(256) k_layer0()
{
    __shared__ float4 se[NPEAK];
    int row = blockIdx.x;
    const float4* ent = g_entries + row * NPEAK;
    for (int i = threadIdx.x; i < NPEAK; i += 256) se[i] = ent[i];
    __syncthreads();

    int t = threadIdx.x;
    if (t >= 250) return;
    float4 acc = *((const float4*)g_c0 + t);

    for (int e = 0; e < NPEAK; e++) {
        float4 E = se[e];
        int cb = __float_as_int(E.w);
        if (cb < 0) continue;   // uniform across block (same row)
        // three fp16 weight rows, 4 cols per thread, 8B loads (row stride 2000B ≡ 0 mod 8)
        uint2 ua = *((const uint2*)(g_w0h + (size_t)(cb    ) * H0) + t);
        uint2 ub = *((const uint2*)(g_w0h + (size_t)(cb + 1) * H0) + t);
        uint2 uc = *((const uint2*)(g_w0h + (size_t)(cb + 2) * H0) + t);
        float2 a01 = __half22float2(*(const __half2*)&ua.x);
        float2 a23 = __half22float2(*(const __half2*)&ua.y);
        float2 b01 = __half22float2(*(const __half2*)&ub.x);
        float2 b23 = __half22float2(*(const __half2*)&ub.y);
        float2 c01 = __half22float2(*(const __half2*)&uc.x);
        float2 c23 = __half22float2(*(const __half2*)&uc.y);
        acc.x += E.x * a01.x + E.y * b01.x + E.z * c01.x;
        acc.y += E.x * a01.y + E.y * b01.y + E.z * c01.y;
        acc.z += E.x * a23.x + E.y * b23.x + E.z * c23.x;
        acc.w += E.x * a23.y + E.y * b23.y + E.z * c23.y;
    }
    acc.x = fmaxf(acc.x, 0.f);
    acc.y = fmaxf(acc.y, 0.f);
    acc.z = fmaxf(acc.z, 0.f);
    acc.w = fmaxf(acc.w, 0.f);
    *((float4*)(g_h0 + row * H0) + t) = acc;
}

// -------------------- K4: double-buffered SGEMM: C = act(A@W + bias) ----------
// A: [M,K] row-major, W: [K,N] row-major. BM=BN=64, BK=8, 256 threads, 4x4/thread.
// M % 64 == 0 and K % 8 == 0 guaranteed here; N guarded.
__global__ void __launch_bounds__(256) k_sgemm(
    const float* __restrict__ A, const float* __restrict__ W,
    const float* __restrict__ bias, float* __restrict__ C,
    int M, int K, int N, int relu)
{
    __shared__ float As[2][8][68];
    __shared__ float Ws[2][8][68];
    int t = threadIdx.x;
    int m0 = blockIdx.y * 64;
    int n0 = blockIdx.x * 64;
    int tx = t & 15, ty = t >> 4;

    int am = t >> 2;          // 0..63
    int ak = (t & 3) * 2;     // 0,2,4,6
    int wk = t >> 5;          // 0..7
    int wn = (t & 31) * 2;    // 0..62
    bool wok = (n0 + wn) < N; // wn+1 < N too since N is even and wn even

    const float* Aptr = A + (m0 + am) * K + ak;
    const float* Wptr = W + wk * N + n0 + wn;

    float acc[4][4];
    #pragma unroll
    for (int i = 0; i < 4; i++)
        #pragma unroll
        for (int j = 0; j < 4; j++) acc[i][j] = 0.f;

    // prologue: load tile 0
    float2 av = *(const float2*)(Aptr);
    float2 wv = wok ? *(const float2*)(Wptr) : make_float2(0.f, 0.f);
    As[0][ak][am] = av.x;  As[0][ak + 1][am] = av.y;
    Ws[0][wk][wn] = wv.x;  Ws[0][wk][wn + 1] = wv.y;
    __syncthreads();

    int buf = 0;
    for (int k0 = 8; k0 < K; k0 += 8) {
        // prefetch next tile from global
        av = *(const float2*)(Aptr + k0);
        wv = wok ? *(const float2*)(Wptr + (size_t)k0 * N) : make_float2(0.f, 0.f);

        // compute on current buffer
        #pragma unroll
        for (int kk = 0; kk < 8; kk++) {
            float4 a = *(const float4*)&As[buf][kk][ty * 4];
            float4 b = *(const float4*)&Ws[buf][kk][tx * 4];
            float ar[4] = {a.x, a.y, a.z, a.w};
            float br[4] = {b.x, b.y, b.z, b.w};
            #pragma unroll
            for (int i = 0; i < 4; i++)
                #pragma unroll
                for (int j = 0; j < 4; j++)
                    acc[i][j] += ar[i] * br[j];
        }

        // store prefetched tile into the other buffer
        int nb = buf ^ 1;
        As[nb][ak][am] = av.x;  As[nb][ak + 1][am] = av.y;
        Ws[nb][wk][wn] = wv.x;  Ws[nb][wk][wn + 1] = wv.y;
        __syncthreads();
        buf = nb;
    }

    // last tile
    #pragma unroll
    for (int kk = 0; kk < 8; kk++) {
        float4 a = *(const float4*)&As[buf][kk][ty * 4];
        float4 b = *(const float4*)&Ws[buf][kk][tx * 4];
        float ar[4] = {a.x, a.y, a.z, a.w};
        float br[4] = {b.x, b.y, b.z, b.w};
        #pragma unroll
        for (int i = 0; i < 4; i++)
            #pragma unroll
            for (int j = 0; j < 4; j++)
                acc[i][j] += ar[i] * br[j];
    }

    #pragma unroll
    for (int i = 0; i < 4; i++) {
        int r = m0 + ty * 4 + i;
        #pragma unroll
        for (int j = 0; j < 4; j++) {
            int col = n0 + tx * 4 + j;
            if (col < N) {
                float v = acc[i][j] + bias[col];
                if (relu) v = fmaxf(v, 0.f);
                C[(size_t)r * N + col] = v;
            }
        }
    }
}

// -------------------- K5: pairwise cosine similarity --------------------
__global__ void __launch_bounds__(128) k_cosine(float* __restrict__ out)
{
    int b = blockIdx.x;
    const float* e1 = g_emb + (2 * b) * HE;
    const float* e2 = e1 + HE;
    int t = threadIdx.x;
    float d = 0.f, s1 = 0.f, s2 = 0.f;
    for (int j = t; j < HE; j += 128) {
        float x = e1[j], y = e2[j];
        d += x * y; s1 += x * x; s2 += y * y;
    }
    #pragma unroll
    for (int o = 16; o > 0; o >>= 1) {
        d  += __shfl_down_sync(0xffffffffu, d, o);
        s1 += __shfl_down_sync(0xffffffffu, s1, o);
        s2 += __shfl_down_sync(0xffffffffu, s2, o);
    }
    __shared__ float sd[4], sa[4], sb[4];
    int w = t >> 5;
    if ((t & 31) == 0) { sd[w] = d; sa[w] = s1; sb[w] = s2; }
    __syncthreads();
    if (t == 0) {
        d  = sd[0] + sd[1] + sd[2] + sd[3];
        s1 = sa[0] + sa[1] + sa[2] + sa[3];
        s2 = sb[0] + sb[1] + sb[2] + sb[3];
        float n1 = fmaxf(sqrtf(s1), 1e-6f);
        float n2 = fmaxf(sqrtf(s2), 1e-6f);
        out[b] = d / (n1 * n2);
    }
}

// -------------------- launch --------------------
extern "C" void kernel_launch(void* const* d_in, const int* in_sizes, int n_in,
                              void* d_out, int out_size)
{
    const float* mz       = (const float*)d_in[0];
    const float* inten    = (const float*)d_in[1];
    const float* binner_w = (const float*)d_in[2];
    const float* binner_b = (const float*)d_in[3];
    const float* w0       = (const float*)d_in[4];
    const float* b0       = (const float*)d_in[5];
    const float* w1       = (const float*)d_in[6];
    const float* b1       = (const float*)d_in[7];
    const float* w2       = (const float*)d_in[8];
    const float* b2       = (const float*)d_in[9];
    const float* we       = (const float*)d_in[10];
    const float* be       = (const float*)d_in[11];
    float* out = (float*)d_out;

    k_build<<<NROWS, NPEAK>>>(mz, inten, binner_w);
    k_c0_part<<<C0_CHUNKS, 256>>>(binner_b, w0);
    k_c0_reduce<<<4, 256>>>(b0);
    k_layer0<<<NROWS, 256>>>();

    {
        float *A, *B, *Cc, *E;
        cudaGetSymbolAddress((void**)&A, g_h0);
        cudaGetSymbolAddress((void**)&B, g_h1);
        cudaGetSymbolAddress((void**)&Cc, g_h2);
        cudaGetSymbolAddress((void**)&E, g_emb);
        // h1 = relu(h0 @ w1 + b1)  [512,1000]x[1000,800]
        dim3 grid1((H1 + 63) / 64, NROWS / 64);
        k_sgemm<<<grid1, 256>>>(A, w1, b1, B, NROWS, H0, H1, 1);
        // h2 = relu(h1 @ w2 + b2)  [512,800]x[800,800]
        dim3 grid2((H2 + 63) / 64, NROWS / 64);
        k_sgemm<<<grid2, 256>>>(B, w2, b2, Cc, NROWS, H1, H2, 1);
        // emb = h2 @ we + be       [512,800]x[800,400]
        dim3 grid3((HE + 63) / 64, NROWS / 64);
        k_sgemm<<<grid3, 256>>>(Cc, we, be, E, NROWS, H2, HE, 0);
    }

    k_cosine<<<256, 128>>>(out);
    (void)in_sizes; (void)n_in; (void)out_size;
}

// round 9
// speedup vs baseline: 1.9273x; 1.9273x over previous
#include <cuda_runtime.h>
#include <cuda_fp16.h>
#include <cuda_bf16.h>
#include <stdint.h>
#include <math.h>

// Problem constants
#define NROWS 512          // 256 pairs * 2 spectra
#define NPEAK 512          // peaks per spectrum
#define GROUPS 3333
#define BOUT 9999          // 3333 * 3
#define H0 1000
#define H0P 1024           // padded K for GEMM1
#define H1 800
#define H2 800
#define HE 400
#define C0_CHUNKS 250      // 40 k-rows each

// -------------------- scratch (device globals; no allocation) --------------------
__device__ float4 g_entries[NROWS * NPEAK];                // 4 MB
__device__ float  g_c0_part[C0_CHUNKS * H0];               // 1 MB
__device__ float  g_c0[H0];
__device__ __half g_w0h[BOUT * H0];                        // 20 MB fp16 copy of w0
__device__ __half g_w1h[H0P * H1];                         // padded rows 1000..1023 zero
__device__ __half g_w2h[H1 * H2];
__device__ __half g_weh[H2 * HE];
__device__ __half g_h0h[NROWS * H0P];                      // fp16 h0, padded cols zero
__device__ __half g_h1h[NROWS * H1];
__device__ __half g_h2h[NROWS * H2];
__device__ float  g_emb[NROWS * HE];

// -------------------- K1: build compact per-peak entries --------------------
__global__ void __launch_bounds__(512) k_build(
    const float* __restrict__ mz, const float* __restrict__ inten,
    const float* __restrict__ binner_w)
{
    int row = blockIdx.x;
    int p   = threadIdx.x;
    int idx = row * NPEAK + p;
    float m  = mz[idx];
    float it = inten[idx];
    float fb = __fdiv_rn(m, 0.01f);
    int b = (int)fb;
    float4 e;
    if (m >= 0.0f && m < 1000.0f && b >= 0 && b < GROUPS * 30) {
        int g = b / 30;
        int i = b - g * 30;
        float v = sqrtf(it);              // inten ** 0.5
        const float* bw = binner_w + (g * 30 + i) * 3;
        e = make_float4(v * bw[0], v * bw[1], v * bw[2], __int_as_float(3 * g));
    } else {
        e = make_float4(0.f, 0.f, 0.f, __int_as_float(-1));
    }
    g_entries[idx] = e;
}

// ---- K2a: c0 partials (bbf @ w0) + fused w0 -> fp16 convert. 250 blocks. ----
__global__ void __launch_bounds__(256) k_c0_part(
    const float* __restrict__ bbf, const float* __restrict__ w0)
{
    int c = blockIdx.x;
    int k0 = c * 40;
    int k1 = min(k0 + 40, BOUT);
    int t = threadIdx.x;
    if (t >= 250) return;
    float4 acc = make_float4(0.f, 0.f, 0.f, 0.f);
    for (int k = k0; k < k1; k++) {
        float b = bbf[k];
        float4 w = *((const float4*)(w0 + (size_t)k * H0) + t);
        acc.x += b * w.x; acc.y += b * w.y; acc.z += b * w.z; acc.w += b * w.w;
        __half2 hlo = __floats2half2_rn(w.x, w.y);
        __half2 hhi = __floats2half2_rn(w.z, w.w);
        uint2 u;
        u.x = *(const unsigned int*)&hlo;
        u.y = *(const unsigned int*)&hhi;
        *((uint2*)(g_w0h + (size_t)k * H0) + t) = u;
    }
    *((float4*)(g_c0_part + c * H0) + t) = acc;
}

// -------------------- K2b: c0 = b0 + sum(partials), fixed order --------------------
__global__ void __launch_bounds__(256) k_c0_reduce(const float* __restrict__ b0)
{
    int j = blockIdx.x * 256 + threadIdx.x;
    if (j >= H0) return;
    float s = b0[j];
    #pragma unroll 5
    for (int c = 0; c < C0_CHUNKS; c++) s += g_c0_part[c * H0 + j];
    g_c0[j] = s;
}

// ---- K2c: weight fp32 -> fp16 converter (zero-fills padded tail) ----
__global__ void __launch_bounds__(256) k_wconv(
    const float* __restrict__ src, __half* __restrict__ dst,
    int nsrc4, int ntot4)   // counts of float4 / (4-elem) groups
{
    for (int f = blockIdx.x * blockDim.x + threadIdx.x; f < ntot4;
         f += gridDim.x * blockDim.x) {
        uint2 o;
        if (f < nsrc4) {
            float4 v = ((const float4*)src)[f];
            __half2 lo = __floats2half2_rn(v.x, v.y);
            __half2 hi = __floats2half2_rn(v.z, v.w);
            o.x = *(const unsigned int*)&lo;
            o.y = *(const unsigned int*)&hi;
        } else {
            o = make_uint2(0u, 0u);
        }
        ((uint2*)dst)[f] = o;
    }
}

// ---- K3: layer 0 sparse: h0 = relu(xs @ w0 + c0), fp16 weights, fp16 out ----
__global__ void __launch_bounds__(256) k_layer0()
{
    __shared__ float4 se[NPEAK];
    int row = blockIdx.x;
    const float4* ent = g_entries + row * NPEAK;
    for (int i = threadIdx.x; i < NPEAK; i += 256) se[i] = ent[i];
    __syncthreads();

    int t = threadIdx.x;
    if (t >= 250) {
        // zero cols 1000..1023 (padding for K=1024 GEMM)
        *((uint2*)(g_h0h + (size_t)row * H0P) + t) = make_uint2(0u, 0u);
        return;
    }
    float4 acc = *((const float4*)g_c0 + t);

    for (int e = 0; e < NPEAK; e++) {
        float4 E = se[e];
        int cb = __float_as_int(E.w);
        if (cb < 0) continue;   // uniform across block (same row)
        uint2 ua = *((const uint2*)(g_w0h + (size_t)(cb    ) * H0) + t);
        uint2 ub = *((const uint2*)(g_w0h + (size_t)(cb + 1) * H0) + t);
        uint2 uc = *((const uint2*)(g_w0h + (size_t)(cb + 2) * H0) + t);
        float2 a01 = __half22float2(*(const __half2*)&ua.x);
        float2 a23 = __half22float2(*(const __half2*)&ua.y);
        float2 b01 = __half22float2(*(const __half2*)&ub.x);
        float2 b23 = __half22float2(*(const __half2*)&ub.y);
        float2 c01 = __half22float2(*(const __half2*)&uc.x);
        float2 c23 = __half22float2(*(const __half2*)&uc.y);
        acc.x += E.x * a01.x + E.y * b01.x + E.z * c01.x;
        acc.y += E.x * a01.y + E.y * b01.y + E.z * c01.y;
        acc.z += E.x * a23.x + E.y * b23.x + E.z * c23.x;
        acc.w += E.x * a23.y + E.y * b23.y + E.z * c23.y;
    }
    acc.x = fmaxf(acc.x, 0.f);
    acc.y = fmaxf(acc.y, 0.f);
    acc.z = fmaxf(acc.z, 0.f);
    acc.w = fmaxf(acc.w, 0.f);
    __half2 lo = __floats2half2_rn(acc.x, acc.y);
    __half2 hi = __floats2half2_rn(acc.z, acc.w);
    uint2 o;
    o.x = *(const unsigned int*)&lo;
    o.y = *(const unsigned int*)&hi;
    *((uint2*)(g_h0h + (size_t)row * H0P) + t) = o;
}

// -------------------- K4: fp16 tensor-core GEMM --------------------
// C = act(A @ W + bias). A:[512,Kp] fp16 row-major (Kp%32==0, zero-padded),
// W:[Kp,N] fp16 row-major. BM=64, BN=64, BK=32, 128 threads (4 warps, 2x2),
// warp tile 32x32 via mma.m16n8k16 (2 m-tiles x 4 n-tiles).
#define GA_STRIDE 40   // halves; 80B rows -> conflict-free ldmatrix (gcd(5,8)=1)
#define GB_STRIDE 72   // halves; 144B rows (gcd(9,8)=1)

__device__ __forceinline__ void ldsm_x4(unsigned int addr,
    unsigned int &r0, unsigned int &r1, unsigned int &r2, unsigned int &r3)
{
    asm volatile("ldmatrix.sync.aligned.m8n8.x4.shared.b16 {%0,%1,%2,%3}, [%4];"
        : "=r"(r0), "=r"(r1), "=r"(r2), "=r"(r3) : "r"(addr));
}
__device__ __forceinline__ void ldsm_x4t(unsigned int addr,
    unsigned int &r0, unsigned int &r1, unsigned int &r2, unsigned int &r3)
{
    asm volatile("ldmatrix.sync.aligned.m8n8.x4.trans.shared.b16 {%0,%1,%2,%3}, [%4];"
        : "=r"(r0), "=r"(r1), "=r"(r2), "=r"(r3) : "r"(addr));
}
__device__ __forceinline__ void mma16816(float* c,
    unsigned int a0, unsigned int a1, unsigned int a2, unsigned int a3,
    unsigned int b0, unsigned int b1)
{
    asm volatile("mma.sync.aligned.m16n8k16.row.col.f32.f16.f16.f32 "
        "{%0,%1,%2,%3}, {%4,%5,%6,%7}, {%8,%9}, {%0,%1,%2,%3};"
        : "+f"(c[0]), "+f"(c[1]), "+f"(c[2]), "+f"(c[3])
        : "r"(a0), "r"(a1), "r"(a2), "r"(a3), "r"(b0), "r"(b1));
}

__global__ void __launch_bounds__(128) k_hgemm(
    const __half* __restrict__ A, const __half* __restrict__ W,
    const float* __restrict__ bias, __half* __restrict__ Ch,
    float* __restrict__ Cf, int Kp, int N, int Nout, int relu)
{
    __shared__ __half sA[64 * GA_STRIDE];
    __shared__ __half sB[32 * GB_STRIDE];

    int t = threadIdx.x;
    int m0 = blockIdx.y * 64;
    int n0 = blockIdx.x * 64;
    int lane = t & 31, warp = t >> 5;
    int m_base = (warp >> 1) * 32;
    int n_base = (warp & 1) * 32;

    // global->smem load slots (2 uint4 per thread per tile)
    int ai0 = 2 * t, ai1 = 2 * t + 1;
    int ar0 = ai0 >> 2, ac0 = (ai0 & 3) * 8;
    int ar1 = ai1 >> 2, ac1 = (ai1 & 3) * 8;
    int br0 = ai0 >> 3, bc0 = (ai0 & 7) * 8;
    int br1 = ai1 >> 3, bc1 = (ai1 & 7) * 8;
    bool bp0 = (n0 + bc0) < N;
    bool bp1 = (n0 + bc1) < N;

    // ldmatrix smem addresses
    int mat = lane >> 3, r = lane & 7;
    unsigned int sA_u = (unsigned int)__cvta_generic_to_shared(sA);
    unsigned int sB_u = (unsigned int)__cvta_generic_to_shared(sB);
    unsigned int aaddr[2][2];
    unsigned int baddr[2][2];
    #pragma unroll
    for (int mt = 0; mt < 2; mt++)
        #pragma unroll
        for (int ks = 0; ks < 2; ks++)
            aaddr[mt][ks] = sA_u + (unsigned int)(((m_base + mt * 16 + (mat & 1) * 8 + r)
                            * GA_STRIDE + ks * 16 + (mat >> 1) * 8) * 2);
    #pragma unroll
    for (int pr = 0; pr < 2; pr++)
        #pragma unroll
        for (int ks = 0; ks < 2; ks++)
            baddr[pr][ks] = sB_u + (unsigned int)(((ks * 16 + (mat & 1) * 8 + r)
                            * GB_STRIDE + n_base + pr * 16 + (mat >> 1) * 8) * 2);

    float acc[2][4][4];
    #pragma unroll
    for (int mt = 0; mt < 2; mt++)
        #pragma unroll
        for (int nt = 0; nt < 4; nt++)
            #pragma unroll
            for (int i = 0; i < 4; i++) acc[mt][nt][i] = 0.f;

    const uint4 zero4 = make_uint4(0u, 0u, 0u, 0u);

    for (int k0 = 0; k0 < Kp; k0 += 32) {
        uint4 av0 = *(const uint4*)(A + (size_t)(m0 + ar0) * Kp + k0 + ac0);
        uint4 av1 = *(const uint4*)(A + (size_t)(m0 + ar1) * Kp + k0 + ac1);
        uint4 bv0 = bp0 ? *(const uint4*)(W + (size_t)(k0 + br0) * N + n0 + bc0) : zero4;
        uint4 bv1 = bp1 ? *(const uint4*)(W + (size_t)(k0 + br1) * N + n0 + bc1) : zero4;
        __syncthreads();
        *(uint4*)(sA + ar0 * GA_STRIDE + ac0) = av0;
        *(uint4*)(sA + ar1 * GA_STRIDE + ac1) = av1;
        *(uint4*)(sB + br0 * GB_STRIDE + bc0) = bv0;
        *(uint4*)(sB + br1 * GB_STRIDE + bc1) = bv1;
        __syncthreads();

        #pragma unroll
        for (int ks = 0; ks < 2; ks++) {
            unsigned int af[2][4];
            ldsm_x4(aaddr[0][ks], af[0][0], af[0][1], af[0][2], af[0][3]);
            ldsm_x4(aaddr[1][ks], af[1][0], af[1][1], af[1][2], af[1][3]);
            unsigned int bf[4][2];
            ldsm_x4t(baddr[0][ks], bf[0][0], bf[0][1], bf[1][0], bf[1][1]);
            ldsm_x4t(baddr[1][ks], bf[2][0], bf[2][1], bf[3][0], bf[3][1]);
            #pragma unroll
            for (int mt = 0; mt < 2; mt++)
                #pragma unroll
                for (int nt = 0; nt < 4; nt++)
                    mma16816(acc[mt][nt], af[mt][0], af[mt][1], af[mt][2], af[mt][3],
                             bf[nt][0], bf[nt][1]);
        }
    }

    // epilogue: bias + optional relu; fp16 (chained) or fp32 (final) store
    int gid = lane >> 2, tig = lane & 3;
    #pragma unroll
    for (int mt = 0; mt < 2; mt++) {
        int row0 = m0 + m_base + mt * 16 + gid;
        #pragma unroll
        for (int nt = 0; nt < 4; nt++) {
            int col = n0 + n_base + nt * 8 + tig * 2;
            if (col < N) {
                float bb0 = bias[col], bb1 = bias[col + 1];
                float v0 = acc[mt][nt][0] + bb0;
                float v1 = acc[mt][nt][1] + bb1;
                float v2 = acc[mt][nt][2] + bb0;
                float v3 = acc[mt][nt][3] + bb1;
                if (relu) {
                    v0 = fmaxf(v0, 0.f); v1 = fmaxf(v1, 0.f);
                    v2 = fmaxf(v2, 0.f); v3 = fmaxf(v3, 0.f);
                }
                if (Cf) {
                    *(float2*)(Cf + (size_t)row0 * Nout + col)       = make_float2(v0, v1);
                    *(float2*)(Cf + (size_t)(row0 + 8) * Nout + col) = make_float2(v2, v3);
                } else {
                    __half2 h01 = __floats2half2_rn(v0, v1);
                    __half2 h23 = __floats2half2_rn(v2, v3);
                    *(__half2*)(Ch + (size_t)row0 * Nout + col)       = h01;
                    *(__half2*)(Ch + (size_t)(row0 + 8) * Nout + col) = h23;
                }
            }
        }
    }
}

// -------------------- K5: pairwise cosine similarity --------------------
__global__ void __launch_bounds__(128) k_cosine(float* __restrict__ out)
{
    int b = blockIdx.x;
    const float* e1 = g_emb + (2 * b) * HE;
    const float* e2 = e1 + HE;
    int t = threadIdx.x;
    float d = 0.f, s1 = 0.f, s2 = 0.f;
    for (int j = t; j < HE; j += 128) {
        float x = e1[j], y = e2[j];
        d += x * y; s1 += x * x; s2 += y * y;
    }
    #pragma unroll
    for (int o = 16; o > 0; o >>= 1) {
        d  += __shfl_down_sync(0xffffffffu, d, o);
        s1 += __shfl_down_sync(0xffffffffu, s1, o);
        s2 += __shfl_down_sync(0xffffffffu, s2, o);
    }
    __shared__ float sd[4], sa[4], sb[4];
    int w = t >> 5;
    if ((t & 31) == 0) { sd[w] = d; sa[w] = s1; sb[w] = s2; }
    __syncthreads();
    if (t == 0) {
        d  = sd[0] + sd[1] + sd[2] + sd[3];
        s1 = sa[0] + sa[1] + sa[2] + sa[3];
        s2 = sb[0] + sb[1] + sb[2] + sb[3];
        float n1 = fmaxf(sqrtf(s1), 1e-6f);
        float n2 = fmaxf(sqrtf(s2), 1e-6f);
        out[b] = d / (n1 * n2);
    }
}

// -------------------- launch --------------------
extern "C" void kernel_launch(void* const* d_in, const int* in_sizes, int n_in,
                              void* d_out, int out_size)
{
    const float* mz       = (const float*)d_in[0];
    const float* inten    = (const float*)d_in[1];
    const float* binner_w = (const float*)d_in[2];
    const float* binner_b = (const float*)d_in[3];
    const float* w0       = (const float*)d_in[4];
    const float* b0       = (const float*)d_in[5];
    const float* w1       = (const float*)d_in[6];
    const float* b1       = (const float*)d_in[7];
    const float* w2       = (const float*)d_in[8];
    const float* b2       = (const float*)d_in[9];
    const float* we       = (const float*)d_in[10];
    const float* be       = (const float*)d_in[11];
    float* out = (float*)d_out;

    __half *w1h, *w2h, *weh, *h0h, *h1h, *h2h;
    float* emb;
    cudaGetSymbolAddress((void**)&w1h, g_w1h);
    cudaGetSymbolAddress((void**)&w2h, g_w2h);
    cudaGetSymbolAddress((void**)&weh, g_weh);
    cudaGetSymbolAddress((void**)&h0h, g_h0h);
    cudaGetSymbolAddress((void**)&h1h, g_h1h);
    cudaGetSymbolAddress((void**)&h2h, g_h2h);
    cudaGetSymbolAddress((void**)&emb, g_emb);

    k_build<<<NROWS, NPEAK>>>(mz, inten, binner_w);
    k_c0_part<<<C0_CHUNKS, 256>>>(binner_b, w0);
    k_c0_reduce<<<4, 256>>>(b0);
    // weight conversions (independent of the above)
    k_wconv<<<256, 256>>>(w1, w1h, (H0 * H1) / 4, (H0P * H1) / 4);
    k_wconv<<<256, 256>>>(w2, w2h, (H1 * H2) / 4, (H1 * H2) / 4);
    k_wconv<<<128, 256>>>(we, weh, (H2 * HE) / 4, (H2 * HE) / 4);

    k_layer0<<<NROWS, 256>>>();

    // h1 = relu(h0 @ w1 + b1): A [512,1024] fp16, W [1024,800]
    {
        dim3 g1((H1 + 63) / 64, NROWS / 64);
        k_hgemm<<<g1, 128>>>(h0h, w1h, b1, h1h, nullptr, H0P, H1, H1, 1);
        dim3 g2((H2 + 63) / 64, NROWS / 64);
        k_hgemm<<<g2, 128>>>(h1h, w2h, b2, h2h, nullptr, H1, H2, H2, 1);
        dim3 g3((HE + 63) / 64, NROWS / 64);
        k_hgemm<<<g3, 128>>>(h2h, weh, be, nullptr, emb, H2, HE, HE, 0);
    }

    k_cosine<<<256, 128>>>(out);
    (void)in_sizes; (void)n_in; (void)out_size;
}

// round 14
// speedup vs baseline: 2.1351x; 1.1079x over previous
#include <cuda_runtime.h>
#include <cuda_fp16.h>
#include <cuda_bf16.h>
#include <stdint.h>
#include <math.h>

// Problem constants
#define NROWS 512          // 256 pairs * 2 spectra
#define NPEAK 512          // peaks per spectrum
#define GROUPS 3333
#define BOUT 9999          // 3333 * 3
#define H0 1000
#define H0P 1024           // padded K for GEMM1
#define H1 800
#define H2 800
#define HE 400
#define C0_CHUNKS 500      // 20 k-rows each
#define C0_S2 10           // stage-2 groups (50 chunks each)

// -------------------- scratch (device globals; no allocation) --------------------
__device__ float4 g_entries[NROWS * NPEAK];                // compacted per row
__device__ int    g_cnt[NROWS];
__device__ float  g_c0_part[C0_CHUNKS * H0];               // 2 MB
__device__ float  g_c0_p2[C0_S2 * H0];
__device__ float  g_c0[H0];
__device__ __half g_w0h[BOUT * H0];                        // 20 MB fp16 copy of w0
__device__ __half g_w1h[H0P * H1];                         // padded rows 1000..1023 zero
__device__ __half g_w2h[H1 * H2];
__device__ __half g_weh[H2 * HE];
__device__ __half g_h0h[NROWS * H0P];                      // fp16 h0, padded cols zero
__device__ __half g_h1h[NROWS * H1];
__device__ __half g_h2h[NROWS * H2];
__device__ float  g_emb[NROWS * HE];

// ---- K1: build per-peak entries, compacted (order-preserving prefix scan) ----
__global__ void __launch_bounds__(512) k_build(
    const float* __restrict__ mz, const float* __restrict__ inten,
    const float* __restrict__ binner_w)
{
    __shared__ int s_wcnt[16];
    __shared__ int s_wbase[16];
    int row = blockIdx.x;
    int p   = threadIdx.x;
    int idx = row * NPEAK + p;
    float m  = mz[idx];
    float it = inten[idx];
    float fb = __fdiv_rn(m, 0.01f);
    int b = (int)fb;
    bool valid = (m >= 0.0f && m < 1000.0f && b >= 0 && b < GROUPS * 30);

    float4 e = make_float4(0.f, 0.f, 0.f, 0.f);
    if (valid) {
        int g = b / 30;
        int i = b - g * 30;
        float v = sqrtf(it);              // inten ** 0.5
        const float* bw = binner_w + (g * 30 + i) * 3;
        e = make_float4(v * bw[0], v * bw[1], v * bw[2], __int_as_float(3 * g));
    }

    // order-preserving compaction within the block (deterministic)
    unsigned int mask = __ballot_sync(0xffffffffu, valid);
    int lane = p & 31, w = p >> 5;
    int pos_in_warp = __popc(mask & ((1u << lane) - 1u));
    if (lane == 0) s_wcnt[w] = __popc(mask);
    __syncthreads();
    if (p == 0) {
        int run = 0;
        #pragma unroll
        for (int i = 0; i < 16; i++) { s_wbase[i] = run; run += s_wcnt[i]; }
        g_cnt[row] = run;
    }
    __syncthreads();
    if (valid)
        g_entries[row * NPEAK + s_wbase[w] + pos_in_warp] = e;
}

// ---- K2a: c0 partials (bbf @ w0) + fused w0 -> fp16 convert. 500 blocks. ----
__global__ void __launch_bounds__(256) k_c0_part(
    const float* __restrict__ bbf, const float* __restrict__ w0)
{
    int c = blockIdx.x;
    int k0 = c * 20;
    int k1 = min(k0 + 20, BOUT);
    int t = threadIdx.x;
    if (t >= 250) return;
    float4 acc = make_float4(0.f, 0.f, 0.f, 0.f);
    for (int k = k0; k < k1; k++) {
        float b = bbf[k];
        float4 w = *((const float4*)(w0 + (size_t)k * H0) + t);
        acc.x += b * w.x; acc.y += b * w.y; acc.z += b * w.z; acc.w += b * w.w;
        __half2 hlo = __floats2half2_rn(w.x, w.y);
        __half2 hhi = __floats2half2_rn(w.z, w.w);
        uint2 u;
        u.x = *(const unsigned int*)&hlo;
        u.y = *(const unsigned int*)&hhi;
        *((uint2*)(g_w0h + (size_t)k * H0) + t) = u;
    }
    *((float4*)(g_c0_part + c * H0) + t) = acc;
}

// ---- K2b: stage-2 reduce: 10 groups of 50 chunks, fixed order ----
__global__ void __launch_bounds__(256) k_c0_r1()
{
    int cgrp = blockIdx.x;           // 0..9
    int jb   = blockIdx.y;           // 0..3
    int t = threadIdx.x;
    if (t >= 250) return;
    int col = jb * 250 + t;
    float s = 0.f;
    int c0c = cgrp * 50;
    #pragma unroll 5
    for (int c = 0; c < 50; c++) s += g_c0_part[(c0c + c) * H0 + col];
    g_c0_p2[cgrp * H0 + col] = s;
}

// ---- K2c: final: c0 = b0 + sum of 10 partials, fixed order ----
__global__ void __launch_bounds__(256) k_c0_r2(const float* __restrict__ b0)
{
    int t = threadIdx.x;
    if (t >= 250) return;
    int col = blockIdx.x * 250 + t;
    float s = b0[col];
    #pragma unroll
    for (int c = 0; c < C0_S2; c++) s += g_c0_p2[c * H0 + col];
    g_c0[col] = s;
}

// ---- K2d: weight fp32 -> fp16 converter (zero-fills padded tail), 1 group/thread ----
__global__ void __launch_bounds__(256) k_wconv(
    const float* __restrict__ src, __half* __restrict__ dst,
    int nsrc4, int ntot4)
{
    int f = blockIdx.x * blockDim.x + threadIdx.x;
    if (f >= ntot4) return;
    uint2 o;
    if (f < nsrc4) {
        float4 v = ((const float4*)src)[f];
        __half2 lo = __floats2half2_rn(v.x, v.y);
        __half2 hi = __floats2half2_rn(v.z, v.w);
        o.x = *(const unsigned int*)&lo;
        o.y = *(const unsigned int*)&hi;
    } else {
        o = make_uint2(0u, 0u);
    }
    ((uint2*)dst)[f] = o;
}

// ---- K3: layer 0 sparse: h0 = relu(xs @ w0 + c0). grid (512 rows, 2 col-halves) ----
__global__ void __launch_bounds__(128) k_layer0()
{
    __shared__ float4 se[NPEAK];
    __shared__ int s_cnt;
    int row = blockIdx.x;
    int half = blockIdx.y;
    int t = threadIdx.x;
    if (t == 0) s_cnt = g_cnt[row];
    const float4* ent = g_entries + row * NPEAK;
    // load up to NPEAK entries (only cnt valid; load all — simpler, still coalesced)
    for (int i = t; i < NPEAK; i += 128) se[i] = ent[i];
    __syncthreads();
    int cnt = s_cnt;

    if (t >= 125) {
        if (half == 1) {
            // zero padding cols 1000..1023 = uint2 idx 250..255
            int base = 250 + (t - 125) * 2;
            *((uint2*)(g_h0h + (size_t)row * H0P) + base)     = make_uint2(0u, 0u);
            *((uint2*)(g_h0h + (size_t)row * H0P) + base + 1) = make_uint2(0u, 0u);
        }
        return;
    }
    int j = half * 125 + t;          // uint2 (4-col) group index, 0..249
    float4 acc = ((const float4*)g_c0)[j];

    int e = 0;
    for (; e + 2 <= cnt; e += 2) {
        float4 E0 = se[e];
        float4 E1 = se[e + 1];
        int cb0 = __float_as_int(E0.w);
        int cb1 = __float_as_int(E1.w);
        uint2 ua0 = *((const uint2*)(g_w0h + (size_t)(cb0    ) * H0) + j);
        uint2 ub0 = *((const uint2*)(g_w0h + (size_t)(cb0 + 1) * H0) + j);
        uint2 uc0 = *((const uint2*)(g_w0h + (size_t)(cb0 + 2) * H0) + j);
        uint2 ua1 = *((const uint2*)(g_w0h + (size_t)(cb1    ) * H0) + j);
        uint2 ub1 = *((const uint2*)(g_w0h + (size_t)(cb1 + 1) * H0) + j);
        uint2 uc1 = *((const uint2*)(g_w0h + (size_t)(cb1 + 2) * H0) + j);
        {
            float2 a01 = __half22float2(*(const __half2*)&ua0.x);
            float2 a23 = __half22float2(*(const __half2*)&ua0.y);
            float2 b01 = __half22float2(*(const __half2*)&ub0.x);
            float2 b23 = __half22float2(*(const __half2*)&ub0.y);
            float2 c01 = __half22float2(*(const __half2*)&uc0.x);
            float2 c23 = __half22float2(*(const __half2*)&uc0.y);
            acc.x += E0.x * a01.x + E0.y * b01.x + E0.z * c01.x;
            acc.y += E0.x * a01.y + E0.y * b01.y + E0.z * c01.y;
            acc.z += E0.x * a23.x + E0.y * b23.x + E0.z * c23.x;
            acc.w += E0.x * a23.y + E0.y * b23.y + E0.z * c23.y;
        }
        {
            float2 a01 = __half22float2(*(const __half2*)&ua1.x);
            float2 a23 = __half22float2(*(const __half2*)&ua1.y);
            float2 b01 = __half22float2(*(const __half2*)&ub1.x);
            float2 b23 = __half22float2(*(const __half2*)&ub1.y);
            float2 c01 = __half22float2(*(const __half2*)&uc1.x);
            float2 c23 = __half22float2(*(const __half2*)&uc1.y);
            acc.x += E1.x * a01.x + E1.y * b01.x + E1.z * c01.x;
            acc.y += E1.x * a01.y + E1.y * b01.y + E1.z * c01.y;
            acc.z += E1.x * a23.x + E1.y * b23.x + E1.z * c23.x;
            acc.w += E1.x * a23.y + E1.y * b23.y + E1.z * c23.y;
        }
    }
    if (e < cnt) {
        float4 E0 = se[e];
        int cb0 = __float_as_int(E0.w);
        uint2 ua0 = *((const uint2*)(g_w0h + (size_t)(cb0    ) * H0) + j);
        uint2 ub0 = *((const uint2*)(g_w0h + (size_t)(cb0 + 1) * H0) + j);
        uint2 uc0 = *((const uint2*)(g_w0h + (size_t)(cb0 + 2) * H0) + j);
        float2 a01 = __half22float2(*(const __half2*)&ua0.x);
        float2 a23 = __half22float2(*(const __half2*)&ua0.y);
        float2 b01 = __half22float2(*(const __half2*)&ub0.x);
        float2 b23 = __half22float2(*(const __half2*)&ub0.y);
        float2 c01 = __half22float2(*(const __half2*)&uc0.x);
        float2 c23 = __half22float2(*(const __half2*)&uc0.y);
        acc.x += E0.x * a01.x + E0.y * b01.x + E0.z * c01.x;
        acc.y += E0.x * a01.y + E0.y * b01.y + E0.z * c01.y;
        acc.z += E0.x * a23.x + E0.y * b23.x + E0.z * c23.x;
        acc.w += E0.x * a23.y + E0.y * b23.y + E0.z * c23.y;
    }
    acc.x = fmaxf(acc.x, 0.f);
    acc.y = fmaxf(acc.y, 0.f);
    acc.z = fmaxf(acc.z, 0.f);
    acc.w = fmaxf(acc.w, 0.f);
    __half2 lo = __floats2half2_rn(acc.x, acc.y);
    __half2 hi = __floats2half2_rn(acc.z, acc.w);
    uint2 o;
    o.x = *(const unsigned int*)&lo;
    o.y = *(const unsigned int*)&hi;
    *((uint2*)(g_h0h + (size_t)row * H0P) + j) = o;
}

// -------------------- K4: fp16 tensor-core GEMM --------------------
#define GA_STRIDE 40   // halves; 80B rows -> conflict-free ldmatrix (gcd(5,8)=1)
#define GB_STRIDE 72   // halves; 144B rows (gcd(9,8)=1)

__device__ __forceinline__ void ldsm_x4(unsigned int addr,
    unsigned int &r0, unsigned int &r1, unsigned int &r2, unsigned int &r3)
{
    asm volatile("ldmatrix.sync.aligned.m8n8.x4.shared.b16 {%0,%1,%2,%3}, [%4];"
        : "=r"(r0), "=r"(r1), "=r"(r2), "=r"(r3) : "r"(addr));
}
__device__ __forceinline__ void ldsm_x4t(unsigned int addr,
    unsigned int &r0, unsigned int &r1, unsigned int &r2, unsigned int &r3)
{
    asm volatile("ldmatrix.sync.aligned.m8n8.x4.trans.shared.b16 {%0,%1,%2,%3}, [%4];"
        : "=r"(r0), "=r"(r1), "=r"(r2), "=r"(r3) : "r"(addr));
}
__device__ __forceinline__ void mma16816(float* c,
    unsigned int a0, unsigned int a1, unsigned int a2, unsigned int a3,
    unsigned int b0, unsigned int b1)
{
    asm volatile("mma.sync.aligned.m16n8k16.row.col.f32.f16.f16.f32 "
        "{%0,%1,%2,%3}, {%4,%5,%6,%7}, {%8,%9}, {%0,%1,%2,%3};"
        : "+f"(c[0]), "+f"(c[1]), "+f"(c[2]), "+f"(c[3])
        : "r"(a0), "r"(a1), "r"(a2), "r"(a3), "r"(b0), "r"(b1));
}

__global__ void __launch_bounds__(128) k_hgemm(
    const __half* __restrict__ A, const __half* __restrict__ W,
    const float* __restrict__ bias, __half* __restrict__ Ch,
    float* __restrict__ Cf, int Kp, int N, int Nout, int relu)
{
    __shared__ __half sA[64 * GA_STRIDE];
    __shared__ __half sB[32 * GB_STRIDE];

    int t = threadIdx.x;
    int m0 = blockIdx.y * 64;
    int n0 = blockIdx.x * 64;
    int lane = t & 31, warp = t >> 5;
    int m_base = (warp >> 1) * 32;
    int n_base = (warp & 1) * 32;

    int ai0 = 2 * t, ai1 = 2 * t + 1;
    int ar0 = ai0 >> 2, ac0 = (ai0 & 3) * 8;
    int ar1 = ai1 >> 2, ac1 = (ai1 & 3) * 8;
    int br0 = ai0 >> 3, bc0 = (ai0 & 7) * 8;
    int br1 = ai1 >> 3, bc1 = (ai1 & 7) * 8;
    bool bp0 = (n0 + bc0) < N;
    bool bp1 = (n0 + bc1) < N;

    int mat = lane >> 3, r = lane & 7;
    unsigned int sA_u = (unsigned int)__cvta_generic_to_shared(sA);
    unsigned int sB_u = (unsigned int)__cvta_generic_to_shared(sB);
    unsigned int aaddr[2][2];
    unsigned int baddr[2][2];
    #pragma unroll
    for (int mt = 0; mt < 2; mt++)
        #pragma unroll
        for (int ks = 0; ks < 2; ks++)
            aaddr[mt][ks] = sA_u + (unsigned int)(((m_base + mt * 16 + (mat & 1) * 8 + r)
                            * GA_STRIDE + ks * 16 + (mat >> 1) * 8) * 2);
    #pragma unroll
    for (int pr = 0; pr < 2; pr++)
        #pragma unroll
        for (int ks = 0; ks < 2; ks++)
            baddr[pr][ks] = sB_u + (unsigned int)(((ks * 16 + (mat & 1) * 8 + r)
                            * GB_STRIDE + n_base + pr * 16 + (mat >> 1) * 8) * 2);

    float acc[2][4][4];
    #pragma unroll
    for (int mt = 0; mt < 2; mt++)
        #pragma unroll
        for (int nt = 0; nt < 4; nt++)
            #pragma unroll
            for (int i = 0; i < 4; i++) acc[mt][nt][i] = 0.f;

    const uint4 zero4 = make_uint4(0u, 0u, 0u, 0u);

    for (int k0 = 0; k0 < Kp; k0 += 32) {
        uint4 av0 = *(const uint4*)(A + (size_t)(m0 + ar0) * Kp + k0 + ac0);
        uint4 av1 = *(const uint4*)(A + (size_t)(m0 + ar1) * Kp + k0 + ac1);
        uint4 bv0 = bp0 ? *(const uint4*)(W + (size_t)(k0 + br0) * N + n0 + bc0) : zero4;
        uint4 bv1 = bp1 ? *(const uint4*)(W + (size_t)(k0 + br1) * N + n0 + bc1) : zero4;
        __syncthreads();
        *(uint4*)(sA + ar0 * GA_STRIDE + ac0) = av0;
        *(uint4*)(sA + ar1 * GA_STRIDE + ac1) = av1;
        *(uint4*)(sB + br0 * GB_STRIDE + bc0) = bv0;
        *(uint4*)(sB + br1 * GB_STRIDE + bc1) = bv1;
        __syncthreads();

        #pragma unroll
        for (int ks = 0; ks < 2; ks++) {
            unsigned int af[2][4];
            ldsm_x4(aaddr[0][ks], af[0][0], af[0][1], af[0][2], af[0][3]);
            ldsm_x4(aaddr[1][ks], af[1][0], af[1][1], af[1][2], af[1][3]);
            unsigned int bf[4][2];
            ldsm_x4t(baddr[0][ks], bf[0][0], bf[0][1], bf[1][0], bf[1][1]);
            ldsm_x4t(baddr[1][ks], bf[2][0], bf[2][1], bf[3][0], bf[3][1]);
            #pragma unroll
            for (int mt = 0; mt < 2; mt++)
                #pragma unroll
                for (int nt = 0; nt < 4; nt++)
                    mma16816(acc[mt][nt], af[mt][0], af[mt][1], af[mt][2], af[mt][3],
                             bf[nt][0], bf[nt][1]);
        }
    }

    int gid = lane >> 2, tig = lane & 3;
    #pragma unroll
    for (int mt = 0; mt < 2; mt++) {
        int row0 = m0 + m_base + mt * 16 + gid;
        #pragma unroll
        for (int nt = 0; nt < 4; nt++) {
            int col = n0 + n_base + nt * 8 + tig * 2;
            if (col < N) {
                float bb0 = bias[col], bb1 = bias[col + 1];
                float v0 = acc[mt][nt][0] + bb0;
                float v1 = acc[mt][nt][1] + bb1;
                float v2 = acc[mt][nt][2] + bb0;
                float v3 = acc[mt][nt][3] + bb1;
                if (relu) {
                    v0 = fmaxf(v0, 0.f); v1 = fmaxf(v1, 0.f);
                    v2 = fmaxf(v2, 0.f); v3 = fmaxf(v3, 0.f);
                }
                if (Cf) {
                    *(float2*)(Cf + (size_t)row0 * Nout + col)       = make_float2(v0, v1);
                    *(float2*)(Cf + (size_t)(row0 + 8) * Nout + col) = make_float2(v2, v3);
                } else {
                    __half2 h01 = __floats2half2_rn(v0, v1);
                    __half2 h23 = __floats2half2_rn(v2, v3);
                    *(__half2*)(Ch + (size_t)row0 * Nout + col)       = h01;
                    *(__half2*)(Ch + (size_t)(row0 + 8) * Nout + col) = h23;
                }
            }
        }
    }
}

// -------------------- K5: pairwise cosine similarity --------------------
__global__ void __launch_bounds__(128) k_cosine(float* __restrict__ out)
{
    int b = blockIdx.x;
    const float* e1 = g_emb + (2 * b) * HE;
    const float* e2 = e1 + HE;
    int t = threadIdx.x;
    float d = 0.f, s1 = 0.f, s2 = 0.f;
    for (int j = t; j < HE; j += 128) {
        float x = e1[j], y = e2[j];
        d += x * y; s1 += x * x; s2 += y * y;
    }
    #pragma unroll
    for (int o = 16; o > 0; o >>= 1) {
        d  += __shfl_down_sync(0xffffffffu, d, o);
        s1 += __shfl_down_sync(0xffffffffu, s1, o);
        s2 += __shfl_down_sync(0xffffffffu, s2, o);
    }
    __shared__ float sd[4], sa[4], sb[4];
    int w = t >> 5;
    if ((t & 31) == 0) { sd[w] = d; sa[w] = s1; sb[w] = s2; }
    __syncthreads();
    if (t == 0) {
        d  = sd[0] + sd[1] + sd[2] + sd[3];
        s1 = sa[0] + sa[1] + sa[2] + sa[3];
        s2 = sb[0] + sb[1] + sb[2] + sb[3];
        float n1 = fmaxf(sqrtf(s1), 1e-6f);
        float n2 = fmaxf(sqrtf(s2), 1e-6f);
        out[b] = d / (n1 * n2);
    }
}

// -------------------- launch --------------------
extern "C" void kernel_launch(void* const* d_in, const int* in_sizes, int n_in,
                              void* d_out, int out_size)
{
    const float* mz       = (const float*)d_in[0];
    const float* inten    = (const float*)d_in[1];
    const float* binner_w = (const float*)d_in[2];
    const float* binner_b = (const float*)d_in[3];
    const float* w0       = (const float*)d_in[4];
    const float* b0       = (const float*)d_in[5];
    const float* w1       = (const float*)d_in[6];
    const float* b1       = (const float*)d_in[7];
    const float* w2       = (const float*)d_in[8];
    const float* b2       = (const float*)d_in[9];
    const float* we       = (const float*)d_in[10];
    const float* be       = (const float*)d_in[11];
    float* out = (float*)d_out;

    __half *w1h, *w2h, *weh, *h0h, *h1h, *h2h;
    float* emb;
    cudaGetSymbolAddress((void**)&w1h, g_w1h);
    cudaGetSymbolAddress((void**)&w2h, g_w2h);
    cudaGetSymbolAddress((void**)&weh, g_weh);
    cudaGetSymbolAddress((void**)&h0h, g_h0h);
    cudaGetSymbolAddress((void**)&h1h, g_h1h);
    cudaGetSymbolAddress((void**)&h2h, g_h2h);
    cudaGetSymbolAddress((void**)&emb, g_emb);

    k_build<<<NROWS, NPEAK>>>(mz, inten, binner_w);
    k_c0_part<<<C0_CHUNKS, 256>>>(binner_b, w0);
    {
        dim3 gr1(C0_S2, 4);
        k_c0_r1<<<gr1, 256>>>();
        k_c0_r2<<<4, 256>>>(b0);
    }
    // weight conversions (one uint2-group per thread, exact grids)
    k_wconv<<<(H0P * H1 / 4 + 255) / 256, 256>>>(w1, w1h, (H0 * H1) / 4, (H0P * H1) / 4);
    k_wconv<<<(H1 * H2 / 4 + 255) / 256, 256>>>(w2, w2h, (H1 * H2) / 4, (H1 * H2) / 4);
    k_wconv<<<(H2 * HE / 4 + 255) / 256, 256>>>(we, weh, (H2 * HE) / 4, (H2 * HE) / 4);

    {
        dim3 gl0(NROWS, 2);
        k_layer0<<<gl0, 128>>>();
    }

    {
        dim3 g1((H1 + 63) / 64, NROWS / 64);
        k_hgemm<<<g1, 128>>>(h0h, w1h, b1, h1h, nullptr, H0P, H1, H1, 1);
        dim3 g2((H2 + 63) / 64, NROWS / 64);
        k_hgemm<<<g2, 128>>>(h1h, w2h, b2, h2h, nullptr, H1, H2, H2, 1);
        dim3 g3((HE + 63) / 64, NROWS / 64);
        k_hgemm<<<g3, 128>>>(h2h, weh, be, nullptr, emb, H2, HE, HE, 0);
    }

    k_cosine<<<256, 128>>>(out);
    (void)in_sizes; (void)n_in; (void)out_size;
}